// round 10
// baseline (speedup 1.0000x reference)
#include <cuda_runtime.h>
#include <cuda_bf16.h>
#include <math.h>

#define N_TOK 32768
#define DIM 64
#define KCB 4096
#define KSPLIT 4
#define KCHUNK (KCB / KSPLIT)     // 1024

// ---- argmax (mma.sync) tiling ----
#define TQ 128                    // tokens per CTA (8 warps x 16)
#define TN 64                     // codes per stage
#define NSTAGES (KCHUNK / TN)     // 16
#define ASTRIDE 72                // padded bf16 row stride (conflict-free for LDS + LDSM)
#define MARGIN 0.008f             // 2 * hard bf16 dot-error bound (unit vectors)
#define QCAP 4096                 // queue entries per drain-group (overflow -> inline fallback)
#define DRAIN_EVERY 4             // drain queue every 4 stages

// dynamic smem layout (bytes). After A-fragment hoist, the A region is reused
// for queue + best + cnt (aliased; guarded by __syncthreads).
#define SM_A     0                // 128*72*2 = 18432
#define SM_B0    18432            // 64*72*2  = 9216
#define SM_B1    27648            // 9216
#define SM_TOTAL 36864
// aliased into [0,18432) after hoist:
#define SM_QUE   0                // QCAP*4 = 16384
#define SM_BEST  16384            // 128*8  = 1024
#define SM_CNT   17408            // 4

// -------- scratch (no allocations allowed) --------
__device__ float g_fn[N_TOK * DIM];
__device__ __nv_bfloat16 g_fnb[N_TOK * DIM];
__device__ __nv_bfloat16 g_embb[KCB * DIM];
__device__ float g_cand_v[KSPLIT * N_TOK];
__device__ int   g_cand_i[KSPLIT * N_TOK];
__device__ int   g_idx[N_TOK];
__device__ int   g_usage[KCB];
__device__ float g_esum[KCB * DIM];
__device__ float g_newcs[KCB];
__device__ float g_scalars[4];

__device__ __forceinline__ float warp_sum(float v) {
#pragma unroll
    for (int o = 16; o > 0; o >>= 1) v += __shfl_xor_sync(0xffffffffu, v, o);
    return v;
}

// Threefry-2x32, 20 rounds (JAX PRNG)
__device__ __forceinline__ void threefry(unsigned k0, unsigned k1, unsigned x0, unsigned x1,
                                         unsigned &o0, unsigned &o1) {
    unsigned ks0 = k0, ks1 = k1, ks2 = k0 ^ k1 ^ 0x1BD11BDAu;
    const int R0[4] = {13, 15, 26, 6};
    const int R1[4] = {17, 29, 16, 24};
    x0 += ks0; x1 += ks1;
    unsigned ks[3] = {ks0, ks1, ks2};
#pragma unroll
    for (int g = 0; g < 5; ++g) {
        const int *R = (g & 1) ? R1 : R0;
#pragma unroll
        for (int r = 0; r < 4; ++r) {
            x0 += x1;
            x1 = (x1 << R[r]) | (x1 >> (32 - R[r]));
            x1 ^= x0;
        }
        x0 += ks[(g + 1) % 3];
        x1 += ks[(g + 2) % 3] + (unsigned)(g + 1);
    }
    o0 = x0; o1 = x1;
}

__device__ __forceinline__ unsigned smem_u32(const void* p) {
    unsigned r;
    asm("{ .reg .u64 t; cvta.to.shared.u64 t, %1; cvt.u32.u64 %0, t; }" : "=r"(r) : "l"(p));
    return r;
}

__device__ __forceinline__ void cp16(unsigned dst, const void* src) {
    asm volatile("cp.async.ca.shared.global [%0], [%1], 16;" :: "r"(dst), "l"(src));
}

// stage one 64-row B tile (row-major bf16, 64/row) into padded smem
__device__ __forceinline__ void stage_B(unsigned sbuf, int kstart, int tid) {
#pragma unroll
    for (int i = 0; i < 2; ++i) {
        int ch = i * 256 + tid;             // 0..511 16B-chunk id
        cp16(sbuf + (unsigned)((ch >> 3) * (ASTRIDE * 2) + (ch & 7) * 16),
             g_embb + (size_t)(kstart + (ch >> 3)) * DIM + (ch & 7) * 8);
    }
}

__device__ __forceinline__ float exact_dot32(int token, int code,
                                             const float* __restrict__ emb) {
    const float4* a = (const float4*)(g_fn + (size_t)token * DIM);
    const float4* b = (const float4*)(emb + (size_t)code * DIM);
    float s = 0.0f;
#pragma unroll
    for (int i = 0; i < 16; ++i) {
        float4 x = a[i], y = b[i];
        s += x.x * y.x; s += x.y * y.y; s += x.z * y.z; s += x.w * y.w;
    }
    return s;
}

__device__ __forceinline__ unsigned long long pack_best(float v, int code) {
    unsigned bits = __float_as_uint(v);
    unsigned key = (bits & 0x80000000u) ? ~bits : (bits | 0x80000000u);
    return ((unsigned long long)key << 32) | (unsigned)(0xFFFFFFFFu - (unsigned)code);
}

// -------- kernel 0: zero scratch accumulators --------
__global__ void zero_kernel() {
    int i = blockIdx.x * blockDim.x + threadIdx.x;
    if (i < KCB * DIM) g_esum[i] = 0.0f;
    if (i < KCB) g_usage[i] = 0;
}

// -------- kernel 1: flat_norm (fp32 + bf16 copies) --------
__global__ void norm_kernel(const float* __restrict__ z_e) {
    int gw = (blockIdx.x * blockDim.x + threadIdx.x) >> 5;
    int lane = threadIdx.x & 31;
    if (gw >= N_TOK) return;
    float2 v = ((const float2*)(z_e + (size_t)gw * DIM))[lane];
    float nrm = sqrtf(warp_sum(v.x * v.x + v.y * v.y));
    float c = fmaxf(nrm, 1e-8f);
    float fx = v.x / c, fy = v.y / c;
    ((float2*)(g_fn + (size_t)gw * DIM))[lane] = make_float2(fx, fy);
    __nv_bfloat162 bb;
    bb.x = __float2bfloat16(fx); bb.y = __float2bfloat16(fy);
    ((__nv_bfloat162*)(g_fnb + (size_t)gw * DIM))[lane] = bb;
}

// -------- kernel 1b: embedding -> bf16 --------
__global__ void embconv_kernel(const float* __restrict__ emb) {
    int i = blockIdx.x * blockDim.x + threadIdx.x;
    if (i < KCB * DIM) g_embb[i] = __float2bfloat16(emb[i]);
}

// -------- kernel 2: HMMA bf16 GEMM argmax, single pass + queued exact refine ---------
// Quad-shared running threshold; ldmatrix B-fragment loads; queue aliased into A region.
__global__ __launch_bounds__(256) void argmax_mma_kernel(const float* __restrict__ emb) {
    extern __shared__ char dynsm[];
    __nv_bfloat16* As = (__nv_bfloat16*)(dynsm + SM_A);
    unsigned* queue = (unsigned*)(dynsm + SM_QUE);                 // aliases As
    unsigned long long* s_best = (unsigned long long*)(dynsm + SM_BEST);
    int* s_cnt = (int*)(dynsm + SM_CNT);

    int tid = threadIdx.x;
    int warp = tid >> 5, lane = tid & 31;
    int g = lane >> 2, c = lane & 3;
    int qblock = blockIdx.x * TQ;
    int kbase = blockIdx.y * KCHUNK;

    unsigned sA = smem_u32(dynsm) + SM_A;
    unsigned sB[2] = { smem_u32(dynsm) + SM_B0, smem_u32(dynsm) + SM_B1 };

    // stage A (128 rows x 64 bf16 -> padded stride 72) and B stage-0
#pragma unroll
    for (int i = 0; i < 4; ++i) {
        int ch = i * 256 + tid;
        cp16(sA + (unsigned)((ch >> 3) * (ASTRIDE * 2) + (ch & 7) * 16),
             g_fnb + (size_t)(qblock + (ch >> 3)) * DIM + (ch & 7) * 8);
    }
    stage_B(sB[0], kbase, tid);
    asm volatile("cp.async.commit_group;" ::: "memory");
    asm volatile("cp.async.wait_group 0;" ::: "memory");
    __syncthreads();

    // hoist A fragments: rows warp*16+g and +8, 4 k-steps x 4 regs
    unsigned a[4][4];
    {
        const __nv_bfloat16* Ar0 = As + (warp * 16 + g) * ASTRIDE;
        const __nv_bfloat16* Ar1 = Ar0 + 8 * ASTRIDE;
#pragma unroll
        for (int k = 0; k < 4; ++k) {
            a[k][0] = *(const unsigned*)(Ar0 + k * 16 + 2 * c);
            a[k][1] = *(const unsigned*)(Ar1 + k * 16 + 2 * c);
            a[k][2] = *(const unsigned*)(Ar0 + k * 16 + 2 * c + 8);
            a[k][3] = *(const unsigned*)(Ar1 + k * 16 + 2 * c + 8);
        }
    }
    __syncthreads();                        // A region now dead -> alias as queue/best

    if (tid < TQ) s_best[tid] = 0ull;
    if (tid == 0) *s_cnt = 0;
    __syncthreads();

    int tokL0 = warp * 16 + g;              // local token rows
    int tokL1 = tokL0 + 8;
    float runM0 = -3.0e38f, runM1 = -3.0e38f;

    for (int s = 0; s < NSTAGES; ++s) {
        if (s + 1 < NSTAGES) {
            stage_B(sB[(s + 1) & 1], kbase + (s + 1) * TN, tid);
            asm volatile("cp.async.commit_group;" ::: "memory");
        }
        unsigned bbuf = sB[s & 1];
        // lane's ldmatrix source row: tile = lane>>3 (8-dim col group), row = lane&7
        unsigned lmrow = bbuf + (unsigned)(((lane & 7) * ASTRIDE + (lane >> 3) * 8) * 2);

#pragma unroll
        for (int t = 0; t < 8; ++t) {
            unsigned fr[8];
            unsigned addr = lmrow + (unsigned)(t * 8 * ASTRIDE * 2);
            asm volatile("ldmatrix.sync.aligned.m8n8.x4.shared.b16 {%0,%1,%2,%3}, [%4];"
                         : "=r"(fr[0]), "=r"(fr[1]), "=r"(fr[2]), "=r"(fr[3]) : "r"(addr));
            asm volatile("ldmatrix.sync.aligned.m8n8.x4.shared.b16 {%0,%1,%2,%3}, [%4];"
                         : "=r"(fr[4]), "=r"(fr[5]), "=r"(fr[6]), "=r"(fr[7])
                         : "r"(addr + 64u));

            float d0 = 0.f, d1 = 0.f, d2 = 0.f, d3 = 0.f;
#pragma unroll
            for (int k = 0; k < 4; ++k) {
                asm("mma.sync.aligned.m16n8k16.row.col.f32.bf16.bf16.f32 "
                    "{%0,%1,%2,%3}, {%4,%5,%6,%7}, {%8,%9}, {%0,%1,%2,%3};"
                    : "+f"(d0), "+f"(d1), "+f"(d2), "+f"(d3)
                    : "r"(a[k][0]), "r"(a[k][1]), "r"(a[k][2]), "r"(a[k][3]),
                      "r"(fr[2 * k]), "r"(fr[2 * k + 1]));
            }

            // quad-shared running max (token-global threshold; superset-safe)
            float m0 = fmaxf(d0, d1), m1 = fmaxf(d2, d3);
            m0 = fmaxf(m0, __shfl_xor_sync(0xffffffffu, m0, 1));
            m0 = fmaxf(m0, __shfl_xor_sync(0xffffffffu, m0, 2));
            m1 = fmaxf(m1, __shfl_xor_sync(0xffffffffu, m1, 1));
            m1 = fmaxf(m1, __shfl_xor_sync(0xffffffffu, m1, 2));
            runM0 = fmaxf(runM0, m0);
            runM1 = fmaxf(runM1, m1);
            float th0 = runM0 - MARGIN, th1 = runM1 - MARGIN;

            int codeL = s * TN + t * 8 + 2 * c;      // chunk-local code of d0/d2
            if (d0 >= th0) {
                int p = atomicAdd(s_cnt, 1);
                if (p < QCAP) queue[p] = (unsigned)((tokL0 << 12) | codeL);
                else {
                    float e = exact_dot32(qblock + tokL0, kbase + codeL, emb);
                    atomicMax(s_best + tokL0, pack_best(e, kbase + codeL));
                }
            }
            if (d1 >= th0) {
                int p = atomicAdd(s_cnt, 1);
                if (p < QCAP) queue[p] = (unsigned)((tokL0 << 12) | (codeL + 1));
                else {
                    float e = exact_dot32(qblock + tokL0, kbase + codeL + 1, emb);
                    atomicMax(s_best + tokL0, pack_best(e, kbase + codeL + 1));
                }
            }
            if (d2 >= th1) {
                int p = atomicAdd(s_cnt, 1);
                if (p < QCAP) queue[p] = (unsigned)((tokL1 << 12) | codeL);
                else {
                    float e = exact_dot32(qblock + tokL1, kbase + codeL, emb);
                    atomicMax(s_best + tokL1, pack_best(e, kbase + codeL));
                }
            }
            if (d3 >= th1) {
                int p = atomicAdd(s_cnt, 1);
                if (p < QCAP) queue[p] = (unsigned)((tokL1 << 12) | (codeL + 1));
                else {
                    float e = exact_dot32(qblock + tokL1, kbase + codeL + 1, emb);
                    atomicMax(s_best + tokL1, pack_best(e, kbase + codeL + 1));
                }
            }
        }

        if (s + 1 < NSTAGES)
            asm volatile("cp.async.wait_group 0;" ::: "memory");
        __syncthreads();

        // drain every DRAIN_EVERY stages (and at the end)
        if ((s & (DRAIN_EVERY - 1)) == (DRAIN_EVERY - 1) || s == NSTAGES - 1) {
            int cnt = *s_cnt;
            int n = cnt < QCAP ? cnt : QCAP;
            for (int i = warp; i < n; i += 8) {
                unsigned e = queue[i];
                int tl = (int)(e >> 12);
                int code = kbase + (int)(e & 0xFFFu);
                float2 x = ((const float2*)(g_fn + (size_t)(qblock + tl) * DIM))[lane];
                float2 y = ((const float2*)(emb + (size_t)code * DIM))[lane];
                float dsum = warp_sum(x.x * y.x + x.y * y.y);
                if (lane == 0) atomicMax(s_best + tl, pack_best(dsum, code));
            }
            __syncthreads();
            if (tid == 0) *s_cnt = 0;
            __syncthreads();
        }
    }

    // write per-token (exact value, index); every token fires at least once (its own max)
    if (tid < TQ) {
        unsigned long long v = s_best[tid];
        unsigned key = (unsigned)(v >> 32);
        unsigned bits = (key & 0x80000000u) ? (key ^ 0x80000000u) : ~key;
        int code = (int)(0xFFFFFFFFu - (unsigned)(v & 0xFFFFFFFFu));
        g_cand_v[blockIdx.y * N_TOK + qblock + tid] = __uint_as_float(bits);
        g_cand_i[blockIdx.y * N_TOK + qblock + tid] = code;
    }
}

// -------- kernel 3: merge K-split candidates --------
__global__ void merge_kernel(float* __restrict__ o_idx) {
    int n = blockIdx.x * blockDim.x + threadIdx.x;
    if (n >= N_TOK) return;
    float bv = g_cand_v[n]; int bi = g_cand_i[n];
#pragma unroll
    for (int s = 1; s < KSPLIT; ++s) {
        float v = g_cand_v[s * N_TOK + n];
        int i = g_cand_i[s * N_TOK + n];
        if (v > bv || (v == bv && i < bi)) { bv = v; bi = i; }
    }
    g_idx[n] = bi;
    o_idx[n] = (float)bi;
}

// -------- kernel 4: gather z_q / z_q_st, scatter usage + embed_sum --------
__global__ void gather_kernel(const float* __restrict__ z_e, const float* __restrict__ emb,
                              float* __restrict__ o_zqst, float* __restrict__ o_zq) {
    int gw = (blockIdx.x * blockDim.x + threadIdx.x) >> 5;
    int lane = threadIdx.x & 31;
    if (gw >= N_TOK) return;
    int idx = g_idx[gw];
    float2 v = ((const float2*)(emb + (size_t)idx * DIM))[lane];
    float2 ze = ((const float2*)(z_e + (size_t)gw * DIM))[lane];
    ((float2*)(o_zq + (size_t)gw * DIM))[lane] = v;
    ((float2*)(o_zqst + (size_t)gw * DIM))[lane] =
        make_float2(ze.x + (v.x - ze.x), ze.y + (v.y - ze.y));
    if (lane == 0) atomicAdd(&g_usage[idx], 1);
    float2 f = ((const float2*)(g_fn + (size_t)gw * DIM))[lane];
    atomicAdd(&g_esum[(size_t)idx * DIM + lane * 2 + 0], f.x);
    atomicAdd(&g_esum[(size_t)idx * DIM + lane * 2 + 1], f.y);
}

// -------- kernel 5: stats (perplexity, dead_ratio), new_cs, n = sum(new_cs) --------
__global__ void stats_kernel(const float* __restrict__ ema_cs,
                             float* __restrict__ o_stats, float* __restrict__ o_ncs) {
    __shared__ float sm[1024];
    int tid = threadIdx.x;
    float ent = 0.0f, dead = 0.0f, nsum = 0.0f;
    for (int k = tid; k < KCB; k += 1024) {
        float u = (float)g_usage[k];
        float pb = u * (1.0f / 32768.0f);
        if (u > 0.0f) ent += pb * logf(pb);
        else dead += 1.0f;
        float ncs = 0.99f * ema_cs[k] + 0.01f * u;
        g_newcs[k] = ncs;
        o_ncs[k] = ncs;
        nsum += ncs;
    }
    sm[tid] = ent; __syncthreads();
    for (int s = 512; s > 0; s >>= 1) { if (tid < s) sm[tid] += sm[tid + s]; __syncthreads(); }
    float tot_ent = sm[0]; __syncthreads();
    sm[tid] = dead; __syncthreads();
    for (int s = 512; s > 0; s >>= 1) { if (tid < s) sm[tid] += sm[tid + s]; __syncthreads(); }
    float tot_dead = sm[0]; __syncthreads();
    sm[tid] = nsum; __syncthreads();
    for (int s = 512; s > 0; s >>= 1) { if (tid < s) sm[tid] += sm[tid + s]; __syncthreads(); }
    if (tid == 0) {
        o_stats[0] = expf(-tot_ent);
        o_stats[1] = tot_dead * (1.0f / (float)KCB);
        g_scalars[0] = sm[0];
    }
}

// -------- kernel 6: EMA embedding update + normalize + dead-code reinit --------
__global__ void embed_kernel(const float* __restrict__ ema_emb,
                             float* __restrict__ o_nemb, float* __restrict__ o_nema) {
    int gw = (blockIdx.x * blockDim.x + threadIdx.x) >> 5;
    int lane = threadIdx.x & 31;
    if (gw >= KCB) return;
    int k = gw;
    float2 ee = ((const float2*)(ema_emb + (size_t)k * DIM))[lane];
    float2 es = ((const float2*)(g_esum + (size_t)k * DIM))[lane];
    float2 ne = make_float2(0.99f * ee.x + 0.01f * es.x, 0.99f * ee.y + 0.01f * es.y);
    ((float2*)(o_nema + (size_t)k * DIM))[lane] = ne;

    float n = g_scalars[0];
    float smoothed = (g_newcs[k] + 1e-5f) / (n + 0.04096f);
    float s = fmaxf(smoothed, 1e-5f);
    float vx = ne.x / s, vy = ne.y / s;
    float nrm = sqrtf(warp_sum(vx * vx + vy * vy));
    float c = fmaxf(nrm, 1e-8f);
    float ox = vx / c, oy = vy / c;

    if (g_usage[k] == 0) {
        unsigned a, b, o0, o1;
        threefry(0u, 1u, 0u, 1u, a, b);
        threefry(a, b, 0u, (unsigned)k, o0, o1);
        int r = (int)((o0 ^ o1) & 0x7FFFu);
        float2 f = ((const float2*)(g_fn + (size_t)r * DIM))[lane];
        float fn2 = warp_sum(f.x * f.x + f.y * f.y);
        float cc = fmaxf(sqrtf(fn2), 1e-8f);
        ox = f.x / cc; oy = f.y / cc;
    }
    ((float2*)(o_nemb + (size_t)k * DIM))[lane] = make_float2(ox, oy);
}

extern "C" void kernel_launch(void* const* d_in, const int* in_sizes, int n_in,
                              void* d_out, int out_size) {
    const float* z_e     = (const float*)d_in[0];   // (32,1024,64)
    const float* emb     = (const float*)d_in[1];   // (4096,64)
    const float* ema_cs  = (const float*)d_in[2];   // (4096,)
    const float* ema_emb = (const float*)d_in[3];   // (4096,64)

    float* out = (float*)d_out;
    float* o_zqst  = out;                 // 2,097,152
    float* o_zq    = out + 2097152;       // 2,097,152
    float* o_idx   = out + 4194304;       //    32,768
    float* o_stats = out + 4227072;       //         2
    float* o_nemb  = out + 4227074;       //   262,144
    float* o_ncs   = out + 4489218;       //     4,096
    float* o_nema  = out + 4493314;       //   262,144

    cudaFuncSetAttribute(argmax_mma_kernel, cudaFuncAttributeMaxDynamicSharedMemorySize,
                         SM_TOTAL);

    zero_kernel<<<(KCB * DIM + 255) / 256, 256>>>();
    norm_kernel<<<(N_TOK * 32) / 256, 256>>>(z_e);
    embconv_kernel<<<(KCB * DIM + 255) / 256, 256>>>(emb);
    dim3 ag(N_TOK / TQ, KSPLIT);
    argmax_mma_kernel<<<ag, 256, SM_TOTAL>>>(emb);
    merge_kernel<<<(N_TOK + 255) / 256, 256>>>(o_idx);
    gather_kernel<<<(N_TOK * 32) / 256, 256>>>(z_e, emb, o_zqst, o_zq);
    stats_kernel<<<1, 1024>>>(ema_cs, o_stats, o_ncs);
    embed_kernel<<<(KCB * 32) / 256, 256>>>(ema_emb, o_nemb, o_nema);
}

// round 14
// speedup vs baseline: 1.1299x; 1.1299x over previous
#include <cuda_runtime.h>
#include <cuda_bf16.h>
#include <math.h>

#define N_TOK 32768
#define DIM 64
#define KCB 4096
#define KSPLIT 4
#define KCHUNK (KCB / KSPLIT)     // 1024

// ---- argmax (mma.sync) tiling ----
#define TQ 128                    // tokens per CTA (8 warps x 16)
#define TN 64                     // codes per stage
#define NSTAGES (KCHUNK / TN)     // 16
#define ASTRIDE 72                // padded bf16 row stride (conflict-free for LDS + LDSM)
#define MARGIN 0.008f             // 2 * hard bf16 dot-error bound (unit vectors)
#define QCAP 4096                 // queue entries per drain-group (overflow -> inline fallback)
#define DRAIN_EVERY 4             // drain queue every 4 stages

// dynamic smem layout (bytes). After A-fragment hoist, the A region is reused
// for queue + best + cnt (aliased; guarded by __syncthreads).
#define SM_A     0                // 128*72*2 = 18432
#define SM_B0    18432            // 64*72*2  = 9216
#define SM_B1    27648            // 9216
#define SM_TOTAL 36864
// aliased into [0,18432) after hoist:
#define SM_QUE   0                // QCAP*4 = 16384
#define SM_BEST  16384            // 128*8  = 1024
#define SM_CNT   17408            // 4

// -------- scratch (no allocations allowed) --------
__device__ float g_fn[N_TOK * DIM];
__device__ __nv_bfloat16 g_fnb[N_TOK * DIM];
__device__ __nv_bfloat16 g_embb[KCB * DIM];
__device__ float g_cand_v[KSPLIT * N_TOK];
__device__ int   g_cand_i[KSPLIT * N_TOK];
__device__ int   g_idx[N_TOK];
__device__ int   g_usage[KCB];
__device__ float g_esum[KCB * DIM];
__device__ float g_newcs[KCB];
__device__ float g_scalars[4];

__device__ __forceinline__ float warp_sum(float v) {
#pragma unroll
    for (int o = 16; o > 0; o >>= 1) v += __shfl_xor_sync(0xffffffffu, v, o);
    return v;
}

// Threefry-2x32, 20 rounds (JAX PRNG)
__device__ __forceinline__ void threefry(unsigned k0, unsigned k1, unsigned x0, unsigned x1,
                                         unsigned &o0, unsigned &o1) {
    unsigned ks0 = k0, ks1 = k1, ks2 = k0 ^ k1 ^ 0x1BD11BDAu;
    const int R0[4] = {13, 15, 26, 6};
    const int R1[4] = {17, 29, 16, 24};
    x0 += ks0; x1 += ks1;
    unsigned ks[3] = {ks0, ks1, ks2};
#pragma unroll
    for (int g = 0; g < 5; ++g) {
        const int *R = (g & 1) ? R1 : R0;
#pragma unroll
        for (int r = 0; r < 4; ++r) {
            x0 += x1;
            x1 = (x1 << R[r]) | (x1 >> (32 - R[r]));
            x1 ^= x0;
        }
        x0 += ks[(g + 1) % 3];
        x1 += ks[(g + 2) % 3] + (unsigned)(g + 1);
    }
    o0 = x0; o1 = x1;
}

__device__ __forceinline__ unsigned smem_u32(const void* p) {
    unsigned r;
    asm("{ .reg .u64 t; cvta.to.shared.u64 t, %1; cvt.u32.u64 %0, t; }" : "=r"(r) : "l"(p));
    return r;
}

__device__ __forceinline__ void cp16(unsigned dst, const void* src) {
    asm volatile("cp.async.ca.shared.global [%0], [%1], 16;" :: "r"(dst), "l"(src));
}

// stage one 64-row B tile (row-major bf16, 64/row) into padded smem
__device__ __forceinline__ void stage_B(unsigned sbuf, int kstart, int tid) {
#pragma unroll
    for (int i = 0; i < 2; ++i) {
        int ch = i * 256 + tid;             // 0..511 16B-chunk id
        cp16(sbuf + (unsigned)((ch >> 3) * (ASTRIDE * 2) + (ch & 7) * 16),
             g_embb + (size_t)(kstart + (ch >> 3)) * DIM + (ch & 7) * 8);
    }
}

__device__ __forceinline__ float exact_dot32(int token, int code,
                                             const float* __restrict__ emb) {
    const float4* a = (const float4*)(g_fn + (size_t)token * DIM);
    const float4* b = (const float4*)(emb + (size_t)code * DIM);
    float s = 0.0f;
#pragma unroll
    for (int i = 0; i < 16; ++i) {
        float4 x = a[i], y = b[i];
        s += x.x * y.x; s += x.y * y.y; s += x.z * y.z; s += x.w * y.w;
    }
    return s;
}

__device__ __forceinline__ unsigned long long pack_best(float v, int code) {
    unsigned bits = __float_as_uint(v);
    unsigned key = (bits & 0x80000000u) ? ~bits : (bits | 0x80000000u);
    return ((unsigned long long)key << 32) | (unsigned)(0xFFFFFFFFu - (unsigned)code);
}

// 16-code MMA group: 4x ldmatrix.x4 + 8 MMA; d[0..3]=codes grp+{2c,2c+1,8+2c,8+2c+1} row g,
// d[4..7]=same codes row g+8.
#define MMA_GROUP16(bbuf, g2, d) do {                                                  \
    unsigned baseA = (bbuf) + (unsigned)((((g2) * 16 + (lane & 7)) * ASTRIDE            \
                                          + (lane >> 3) * 8) * 2);                      \
    unsigned baseB = baseA + (unsigned)(8 * ASTRIDE * 2);                               \
    unsigned frA[8], frB[8];                                                            \
    asm volatile("ldmatrix.sync.aligned.m8n8.x4.shared.b16 {%0,%1,%2,%3}, [%4];"        \
                 : "=r"(frA[0]), "=r"(frA[1]), "=r"(frA[2]), "=r"(frA[3]) : "r"(baseA));\
    asm volatile("ldmatrix.sync.aligned.m8n8.x4.shared.b16 {%0,%1,%2,%3}, [%4];"        \
                 : "=r"(frA[4]), "=r"(frA[5]), "=r"(frA[6]), "=r"(frA[7])               \
                 : "r"(baseA + 64u));                                                   \
    asm volatile("ldmatrix.sync.aligned.m8n8.x4.shared.b16 {%0,%1,%2,%3}, [%4];"        \
                 : "=r"(frB[0]), "=r"(frB[1]), "=r"(frB[2]), "=r"(frB[3]) : "r"(baseB));\
    asm volatile("ldmatrix.sync.aligned.m8n8.x4.shared.b16 {%0,%1,%2,%3}, [%4];"        \
                 : "=r"(frB[4]), "=r"(frB[5]), "=r"(frB[6]), "=r"(frB[7])               \
                 : "r"(baseB + 64u));                                                   \
    d[0]=d[1]=d[2]=d[3]=d[4]=d[5]=d[6]=d[7]=0.f;                                        \
    _Pragma("unroll")                                                                   \
    for (int k = 0; k < 4; ++k) {                                                       \
        asm("mma.sync.aligned.m16n8k16.row.col.f32.bf16.bf16.f32 "                      \
            "{%0,%1,%2,%3}, {%4,%5,%6,%7}, {%8,%9}, {%0,%1,%2,%3};"                     \
            : "+f"(d[0]), "+f"(d[1]), "+f"(d[4]), "+f"(d[5])                            \
            : "r"(a[k][0]), "r"(a[k][1]), "r"(a[k][2]), "r"(a[k][3]),                   \
              "r"(frA[2 * k]), "r"(frA[2 * k + 1]));                                    \
        asm("mma.sync.aligned.m16n8k16.row.col.f32.bf16.bf16.f32 "                      \
            "{%0,%1,%2,%3}, {%4,%5,%6,%7}, {%8,%9}, {%0,%1,%2,%3};"                     \
            : "+f"(d[2]), "+f"(d[3]), "+f"(d[6]), "+f"(d[7])                            \
            : "r"(a[k][0]), "r"(a[k][1]), "r"(a[k][2]), "r"(a[k][3]),                   \
              "r"(frB[2 * k]), "r"(frB[2 * k + 1]));                                    \
    }                                                                                   \
} while (0)

// -------- kernel 0: zero scratch accumulators --------
__global__ void zero_kernel() {
    int i = blockIdx.x * blockDim.x + threadIdx.x;
    if (i < KCB * DIM) g_esum[i] = 0.0f;
    if (i < KCB) g_usage[i] = 0;
}

// -------- kernel 1: flat_norm (fp32 + bf16 copies) --------
__global__ void norm_kernel(const float* __restrict__ z_e) {
    int gw = (blockIdx.x * blockDim.x + threadIdx.x) >> 5;
    int lane = threadIdx.x & 31;
    if (gw >= N_TOK) return;
    float2 v = ((const float2*)(z_e + (size_t)gw * DIM))[lane];
    float nrm = sqrtf(warp_sum(v.x * v.x + v.y * v.y));
    float c = fmaxf(nrm, 1e-8f);
    float fx = v.x / c, fy = v.y / c;
    ((float2*)(g_fn + (size_t)gw * DIM))[lane] = make_float2(fx, fy);
    __nv_bfloat162 bb;
    bb.x = __float2bfloat16(fx); bb.y = __float2bfloat16(fy);
    ((__nv_bfloat162*)(g_fnb + (size_t)gw * DIM))[lane] = bb;
}

// -------- kernel 1b: embedding -> bf16 --------
__global__ void embconv_kernel(const float* __restrict__ emb) {
    int i = blockIdx.x * blockDim.x + threadIdx.x;
    if (i < KCB * DIM) g_embb[i] = __float2bfloat16(emb[i]);
}

// -------- kernel 2: HMMA bf16 GEMM argmax, stage-lagged threshold + queued refine -----
__global__ __launch_bounds__(256) void argmax_mma_kernel(const float* __restrict__ emb) {
    extern __shared__ char dynsm[];
    __nv_bfloat16* As = (__nv_bfloat16*)(dynsm + SM_A);
    unsigned* queue = (unsigned*)(dynsm + SM_QUE);                 // aliases As
    unsigned long long* s_best = (unsigned long long*)(dynsm + SM_BEST);
    int* s_cnt = (int*)(dynsm + SM_CNT);

    int tid = threadIdx.x;
    int warp = tid >> 5, lane = tid & 31;
    int g = lane >> 2, c = lane & 3;
    int qblock = blockIdx.x * TQ;
    int kbase = blockIdx.y * KCHUNK;

    unsigned sA = smem_u32(dynsm) + SM_A;
    unsigned sB[2] = { smem_u32(dynsm) + SM_B0, smem_u32(dynsm) + SM_B1 };

    // stage A and B stage-0
#pragma unroll
    for (int i = 0; i < 4; ++i) {
        int ch = i * 256 + tid;
        cp16(sA + (unsigned)((ch >> 3) * (ASTRIDE * 2) + (ch & 7) * 16),
             g_fnb + (size_t)(qblock + (ch >> 3)) * DIM + (ch & 7) * 8);
    }
    stage_B(sB[0], kbase, tid);
    asm volatile("cp.async.commit_group;" ::: "memory");
    asm volatile("cp.async.wait_group 0;" ::: "memory");
    __syncthreads();

    // hoist A fragments: rows warp*16+g and +8, 4 k-steps x 4 regs
    unsigned a[4][4];
    {
        const __nv_bfloat16* Ar0 = As + (warp * 16 + g) * ASTRIDE;
        const __nv_bfloat16* Ar1 = Ar0 + 8 * ASTRIDE;
#pragma unroll
        for (int k = 0; k < 4; ++k) {
            a[k][0] = *(const unsigned*)(Ar0 + k * 16 + 2 * c);
            a[k][1] = *(const unsigned*)(Ar1 + k * 16 + 2 * c);
            a[k][2] = *(const unsigned*)(Ar0 + k * 16 + 2 * c + 8);
            a[k][3] = *(const unsigned*)(Ar1 + k * 16 + 2 * c + 8);
        }
    }
    __syncthreads();                        // A region now dead -> alias as queue/best

    if (tid < TQ) s_best[tid] = 0ull;
    if (tid == 0) *s_cnt = 0;
    __syncthreads();

    int tokL0 = warp * 16 + g;              // local token rows
    int tokL1 = tokL0 + 8;
    float runM0 = -3.0e38f, runM1 = -3.0e38f;

    // ---- pre-pass over stage 0: max only, seeds the threshold ----
#pragma unroll
    for (int g2 = 0; g2 < 4; ++g2) {
        float d[8];
        MMA_GROUP16(sB[0], g2, d);
        runM0 = fmaxf(runM0, fmaxf(fmaxf(d[0], d[1]), fmaxf(d[2], d[3])));
        runM1 = fmaxf(runM1, fmaxf(fmaxf(d[4], d[5]), fmaxf(d[6], d[7])));
    }
    float th0, th1;
    {
        float m0 = runM0, m1 = runM1;
        m0 = fmaxf(m0, __shfl_xor_sync(0xffffffffu, m0, 1));
        m0 = fmaxf(m0, __shfl_xor_sync(0xffffffffu, m0, 2));
        m1 = fmaxf(m1, __shfl_xor_sync(0xffffffffu, m1, 1));
        m1 = fmaxf(m1, __shfl_xor_sync(0xffffffffu, m1, 2));
        th0 = m0 - MARGIN; th1 = m1 - MARGIN;
    }

    // ---- main loop: all 16 stages with constant-in-stage threshold ----
    for (int s = 0; s < NSTAGES; ++s) {
        if (s + 1 < NSTAGES) {
            stage_B(sB[(s + 1) & 1], kbase + (s + 1) * TN, tid);
            asm volatile("cp.async.commit_group;" ::: "memory");
        }
        unsigned bbuf = sB[s & 1];

#pragma unroll
        for (int g2 = 0; g2 < 4; ++g2) {
            float d[8];
            MMA_GROUP16(bbuf, g2, d);

            float m0 = fmaxf(fmaxf(d[0], d[1]), fmaxf(d[2], d[3]));
            float m1 = fmaxf(fmaxf(d[4], d[5]), fmaxf(d[6], d[7]));
            runM0 = fmaxf(runM0, m0);
            runM1 = fmaxf(runM1, m1);

            if (m0 >= th0 || m1 >= th1) {     // rare guard: this 16-code group has a candidate
                int codeL = s * TN + g2 * 16 + 2 * c;
#pragma unroll
                for (int j = 0; j < 8; ++j) {
                    float th = (j < 4) ? th0 : th1;
                    if (d[j] >= th) {
                        int tl = (j < 4) ? tokL0 : tokL1;
                        int cl = codeL + ((j & 2) ? 8 : 0) + (j & 1);
                        int p = atomicAdd(s_cnt, 1);
                        if (p < QCAP) queue[p] = (unsigned)((tl << 12) | cl);
                        else {
                            float e = exact_dot32(qblock + tl, kbase + cl, emb);
                            atomicMax(s_best + tl, pack_best(e, kbase + cl));
                        }
                    }
                }
            }
        }

        // refresh threshold once per stage (lagged; only grows the candidate superset)
        {
            float m0 = runM0, m1 = runM1;
            m0 = fmaxf(m0, __shfl_xor_sync(0xffffffffu, m0, 1));
            m0 = fmaxf(m0, __shfl_xor_sync(0xffffffffu, m0, 2));
            m1 = fmaxf(m1, __shfl_xor_sync(0xffffffffu, m1, 1));
            m1 = fmaxf(m1, __shfl_xor_sync(0xffffffffu, m1, 2));
            th0 = fmaxf(th0, m0 - MARGIN); th1 = fmaxf(th1, m1 - MARGIN);
        }

        if (s + 1 < NSTAGES)
            asm volatile("cp.async.wait_group 0;" ::: "memory");
        __syncthreads();

        if ((s & (DRAIN_EVERY - 1)) == (DRAIN_EVERY - 1) || s == NSTAGES - 1) {
            int cnt = *s_cnt;
            int n = cnt < QCAP ? cnt : QCAP;
            for (int i = warp; i < n; i += 8) {
                unsigned e = queue[i];
                int tl = (int)(e >> 12);
                int code = kbase + (int)(e & 0xFFFu);
                float2 x = ((const float2*)(g_fn + (size_t)(qblock + tl) * DIM))[lane];
                float2 y = ((const float2*)(emb + (size_t)code * DIM))[lane];
                float dsum = warp_sum(x.x * y.x + x.y * y.y);
                if (lane == 0) atomicMax(s_best + tl, pack_best(dsum, code));
            }
            __syncthreads();
            if (tid == 0) *s_cnt = 0;
            __syncthreads();
        }
    }

    if (tid < TQ) {
        unsigned long long v = s_best[tid];
        unsigned key = (unsigned)(v >> 32);
        unsigned bits = (key & 0x80000000u) ? (key ^ 0x80000000u) : ~key;
        int code = (int)(0xFFFFFFFFu - (unsigned)(v & 0xFFFFFFFFu));
        g_cand_v[blockIdx.y * N_TOK + qblock + tid] = __uint_as_float(bits);
        g_cand_i[blockIdx.y * N_TOK + qblock + tid] = code;
    }
}

// -------- kernel 3: merge K-split candidates --------
__global__ void merge_kernel(float* __restrict__ o_idx) {
    int n = blockIdx.x * blockDim.x + threadIdx.x;
    if (n >= N_TOK) return;
    float bv = g_cand_v[n]; int bi = g_cand_i[n];
#pragma unroll
    for (int s = 1; s < KSPLIT; ++s) {
        float v = g_cand_v[s * N_TOK + n];
        int i = g_cand_i[s * N_TOK + n];
        if (v > bv || (v == bv && i < bi)) { bv = v; bi = i; }
    }
    g_idx[n] = bi;
    o_idx[n] = (float)bi;
}

// -------- kernel 4: gather z_q / z_q_st, scatter usage + embed_sum --------
__global__ void gather_kernel(const float* __restrict__ z_e, const float* __restrict__ emb,
                              float* __restrict__ o_zqst, float* __restrict__ o_zq) {
    int gw = (blockIdx.x * blockDim.x + threadIdx.x) >> 5;
    int lane = threadIdx.x & 31;
    if (gw >= N_TOK) return;
    int idx = g_idx[gw];
    float2 v = ((const float2*)(emb + (size_t)idx * DIM))[lane];
    float2 ze = ((const float2*)(z_e + (size_t)gw * DIM))[lane];
    ((float2*)(o_zq + (size_t)gw * DIM))[lane] = v;
    ((float2*)(o_zqst + (size_t)gw * DIM))[lane] =
        make_float2(ze.x + (v.x - ze.x), ze.y + (v.y - ze.y));
    if (lane == 0) atomicAdd(&g_usage[idx], 1);
    float2 f = ((const float2*)(g_fn + (size_t)gw * DIM))[lane];
    atomicAdd(&g_esum[(size_t)idx * DIM + lane * 2 + 0], f.x);
    atomicAdd(&g_esum[(size_t)idx * DIM + lane * 2 + 1], f.y);
}

// -------- kernel 5: stats (perplexity, dead_ratio), new_cs, n = sum(new_cs) --------
__global__ void stats_kernel(const float* __restrict__ ema_cs,
                             float* __restrict__ o_stats, float* __restrict__ o_ncs) {
    __shared__ float sm[1024];
    int tid = threadIdx.x;
    float ent = 0.0f, dead = 0.0f, nsum = 0.0f;
    for (int k = tid; k < KCB; k += 1024) {
        float u = (float)g_usage[k];
        float pb = u * (1.0f / 32768.0f);
        if (u > 0.0f) ent += pb * logf(pb);
        else dead += 1.0f;
        float ncs = 0.99f * ema_cs[k] + 0.01f * u;
        g_newcs[k] = ncs;
        o_ncs[k] = ncs;
        nsum += ncs;
    }
    sm[tid] = ent; __syncthreads();
    for (int s = 512; s > 0; s >>= 1) { if (tid < s) sm[tid] += sm[tid + s]; __syncthreads(); }
    float tot_ent = sm[0]; __syncthreads();
    sm[tid] = dead; __syncthreads();
    for (int s = 512; s > 0; s >>= 1) { if (tid < s) sm[tid] += sm[tid + s]; __syncthreads(); }
    float tot_dead = sm[0]; __syncthreads();
    sm[tid] = nsum; __syncthreads();
    for (int s = 512; s > 0; s >>= 1) { if (tid < s) sm[tid] += sm[tid + s]; __syncthreads(); }
    if (tid == 0) {
        o_stats[0] = expf(-tot_ent);
        o_stats[1] = tot_dead * (1.0f / (float)KCB);
        g_scalars[0] = sm[0];
    }
}

// -------- kernel 6: EMA embedding update + normalize + dead-code reinit --------
__global__ void embed_kernel(const float* __restrict__ ema_emb,
                             float* __restrict__ o_nemb, float* __restrict__ o_nema) {
    int gw = (blockIdx.x * blockDim.x + threadIdx.x) >> 5;
    int lane = threadIdx.x & 31;
    if (gw >= KCB) return;
    int k = gw;
    float2 ee = ((const float2*)(ema_emb + (size_t)k * DIM))[lane];
    float2 es = ((const float2*)(g_esum + (size_t)k * DIM))[lane];
    float2 ne = make_float2(0.99f * ee.x + 0.01f * es.x, 0.99f * ee.y + 0.01f * es.y);
    ((float2*)(o_nema + (size_t)k * DIM))[lane] = ne;

    float n = g_scalars[0];
    float smoothed = (g_newcs[k] + 1e-5f) / (n + 0.04096f);
    float s = fmaxf(smoothed, 1e-5f);
    float vx = ne.x / s, vy = ne.y / s;
    float nrm = sqrtf(warp_sum(vx * vx + vy * vy));
    float c = fmaxf(nrm, 1e-8f);
    float ox = vx / c, oy = vy / c;

    if (g_usage[k] == 0) {
        unsigned a, b, o0, o1;
        threefry(0u, 1u, 0u, 1u, a, b);
        threefry(a, b, 0u, (unsigned)k, o0, o1);
        int r = (int)((o0 ^ o1) & 0x7FFFu);
        float2 f = ((const float2*)(g_fn + (size_t)r * DIM))[lane];
        float fn2 = warp_sum(f.x * f.x + f.y * f.y);
        float cc = fmaxf(sqrtf(fn2), 1e-8f);
        ox = f.x / cc; oy = f.y / cc;
    }
    ((float2*)(o_nemb + (size_t)k * DIM))[lane] = make_float2(ox, oy);
}

extern "C" void kernel_launch(void* const* d_in, const int* in_sizes, int n_in,
                              void* d_out, int out_size) {
    const float* z_e     = (const float*)d_in[0];   // (32,1024,64)
    const float* emb     = (const float*)d_in[1];   // (4096,64)
    const float* ema_cs  = (const float*)d_in[2];   // (4096,)
    const float* ema_emb = (const float*)d_in[3];   // (4096,64)

    float* out = (float*)d_out;
    float* o_zqst  = out;                 // 2,097,152
    float* o_zq    = out + 2097152;       // 2,097,152
    float* o_idx   = out + 4194304;       //    32,768
    float* o_stats = out + 4227072;       //         2
    float* o_nemb  = out + 4227074;       //   262,144
    float* o_ncs   = out + 4489218;       //     4,096
    float* o_nema  = out + 4493314;       //   262,144

    cudaFuncSetAttribute(argmax_mma_kernel, cudaFuncAttributeMaxDynamicSharedMemorySize,
                         SM_TOTAL);

    zero_kernel<<<(KCB * DIM + 255) / 256, 256>>>();
    norm_kernel<<<(N_TOK * 32) / 256, 256>>>(z_e);
    embconv_kernel<<<(KCB * DIM + 255) / 256, 256>>>(emb);
    dim3 ag(N_TOK / TQ, KSPLIT);
    argmax_mma_kernel<<<ag, 256, SM_TOTAL>>>(emb);
    merge_kernel<<<(N_TOK + 255) / 256, 256>>>(o_idx);
    gather_kernel<<<(N_TOK * 32) / 256, 256>>>(z_e, emb, o_zqst, o_zq);
    stats_kernel<<<1, 1024>>>(ema_cs, o_stats, o_ncs);
    embed_kernel<<<(KCB * 32) / 256, 256>>>(ema_emb, o_nemb, o_nema);
}